// round 5
// baseline (speedup 1.0000x reference)
#include <cuda_runtime.h>
#include <cstdint>
#include <math.h>

// ---------------------------------------------------------------------------
// Problem constants
// ---------------------------------------------------------------------------
#define NB   2
#define S    2048
#define DM   1024
#define NH   16
#define HD   64
#define DFF  4096
#define TOK  (NB * S)
#define LN_EPS 1e-5f

// ---------------------------------------------------------------------------
// Scratch (static device globals; no runtime allocation allowed)
// ---------------------------------------------------------------------------
__device__ float g_xn [(size_t)TOK * DM];
__device__ float g_q  [(size_t)TOK * DM];
__device__ float g_k  [(size_t)TOK * DM];
__device__ float g_v  [(size_t)TOK * DM];
__device__ float g_ao [(size_t)TOK * DM];
__device__ float g_x2 [(size_t)TOK * DM];
__device__ float g_ff [(size_t)TOK * DFF];
__device__ float g_wqt[(size_t)DM * DM];
__device__ float g_wkt[(size_t)DM * DM];
__device__ float g_wvt[(size_t)DM * DM];
__device__ float g_w0t[(size_t)DM * DM];
__device__ float g_w1t[(size_t)DM * DFF];
__device__ float g_w2t[(size_t)DM * DFF];
__device__ float g_vt [(size_t)NB * NH * HD * S];
__device__ float g_s  [(size_t)NB * NH * S * S];   // 512 MB scores/probs

// ---------------------------------------------------------------------------
// Helpers
// ---------------------------------------------------------------------------
__device__ __forceinline__ float to_tf32(float x) {
    uint32_t u;
    asm("cvt.rna.tf32.f32 %0, %1;" : "=r"(u) : "f"(x));
    return __uint_as_float(u);
}
__device__ __forceinline__ void mma_tf32(float* c, const uint32_t* a, const uint32_t* b) {
    asm volatile(
        "mma.sync.aligned.m16n8k8.row.col.f32.tf32.tf32.f32 "
        "{%0,%1,%2,%3}, {%4,%5,%6,%7}, {%8,%9}, {%0,%1,%2,%3};"
        : "+f"(c[0]), "+f"(c[1]), "+f"(c[2]), "+f"(c[3])
        : "r"(a[0]), "r"(a[1]), "r"(a[2]), "r"(a[3]), "r"(b[0]), "r"(b[1]));
}

// ---------------------------------------------------------------------------
// tf32 mma.sync GEMM.  C[M,N] = A[M,K] @ B^T, B stored [N][K] K-major.
// 128(M) x BN tile, BK=16, 256 threads = 8 warps (4 M x 2 N),
// warp tile 32 x (BN/2) = 2 m16-tiles x (BN/16) n8-tiles.
// Double-buffered smem [row][BK+4], register-staged prefetch.
// Batched via blockIdx.z with (inner,outer) strides; zin = inner count.
// ---------------------------------------------------------------------------
template<int BN, bool BIAS, bool RELU, bool RES>
__global__ __launch_bounds__(256) void mma_gemm(
    const float* __restrict__ A, int lda, long long sAi, long long sAo,
    const float* __restrict__ B, int ldb, long long sBi, long long sBo,
    float* __restrict__ C, int ldc, long long sCi, long long sCo,
    const float* __restrict__ bias, const float* __restrict__ res,
    int K, int zin)
{
    constexpr int BM = 128, BK = 16, SK = BK + 4;   // stride 20 -> conflict-free frags
    constexpr int WN = BN / 2;      // per-warp-column N extent (64 or 32)
    constexpr int NT = WN / 8;      // n8 tiles per warp (8 or 4)
    constexpr int BF4 = BN * 4 / 256;  // B float4 loads per thread (2 or 1)

    __shared__ float As[2][BM][SK];
    __shared__ float Bs[2][BN][SK];

    const int tid = threadIdx.x;
    const int wid = tid >> 5, lane = tid & 31;
    const int warpM = wid & 3, warpN = wid >> 2;
    const int r4 = lane >> 2, cq = lane & 3;

    const int zi = (int)(blockIdx.z % zin), zo = (int)(blockIdx.z / zin);
    const float* Ab = A + (size_t)zo * sAo + (size_t)zi * sAi + (size_t)blockIdx.y * BM * lda;
    const float* Bb = B + (size_t)zo * sBo + (size_t)zi * sBi + (size_t)blockIdx.x * BN * ldb;

    // staging map: float4 i -> row = i>>2, k-quad = i&3
    const int srow = tid >> 2, sq = tid & 3;

    float acc[2][NT][4];
    #pragma unroll
    for (int mt = 0; mt < 2; mt++)
        #pragma unroll
        for (int nt = 0; nt < NT; nt++)
            #pragma unroll
            for (int j = 0; j < 4; j++) acc[mt][nt][j] = 0.0f;

    float4 pa[2], pb[2];
    // preload tile 0
    #pragma unroll
    for (int j = 0; j < 2; j++)
        pa[j] = *(const float4*)(Ab + (size_t)(srow + j * 64) * lda + sq * 4);
    #pragma unroll
    for (int j = 0; j < BF4; j++)
        pb[j] = *(const float4*)(Bb + (size_t)(srow + j * 64) * ldb + sq * 4);

    const int nt_iters = K / BK;
    for (int t = 0; t < nt_iters; t++) {
        const int buf = t & 1;
        #pragma unroll
        for (int j = 0; j < 2; j++) {
            float4 f = pa[j];
            f.x = to_tf32(f.x); f.y = to_tf32(f.y);
            f.z = to_tf32(f.z); f.w = to_tf32(f.w);
            *(float4*)&As[buf][srow + j * 64][sq * 4] = f;
        }
        #pragma unroll
        for (int j = 0; j < BF4; j++) {
            float4 f = pb[j];
            f.x = to_tf32(f.x); f.y = to_tf32(f.y);
            f.z = to_tf32(f.z); f.w = to_tf32(f.w);
            *(float4*)&Bs[buf][srow + j * 64][sq * 4] = f;
        }
        __syncthreads();

        if (t + 1 < nt_iters) {
            const float* Ak = Ab + (t + 1) * BK;
            const float* Bk = Bb + (t + 1) * BK;
            #pragma unroll
            for (int j = 0; j < 2; j++)
                pa[j] = *(const float4*)(Ak + (size_t)(srow + j * 64) * lda + sq * 4);
            #pragma unroll
            for (int j = 0; j < BF4; j++)
                pb[j] = *(const float4*)(Bk + (size_t)(srow + j * 64) * ldb + sq * 4);
        }

        const int m0 = warpM * 32;
        const int n0 = warpN * WN;
        #pragma unroll
        for (int ks = 0; ks < 2; ks++) {
            const int k8 = ks * 8;
            uint32_t a[2][4], b[NT][2];
            #pragma unroll
            for (int mt = 0; mt < 2; mt++) {
                const int m = m0 + mt * 16 + r4;
                a[mt][0] = __float_as_uint(As[buf][m    ][k8 + cq]);
                a[mt][1] = __float_as_uint(As[buf][m + 8][k8 + cq]);
                a[mt][2] = __float_as_uint(As[buf][m    ][k8 + cq + 4]);
                a[mt][3] = __float_as_uint(As[buf][m + 8][k8 + cq + 4]);
            }
            #pragma unroll
            for (int nt = 0; nt < NT; nt++) {
                const int n = n0 + nt * 8 + r4;
                b[nt][0] = __float_as_uint(Bs[buf][n][k8 + cq]);
                b[nt][1] = __float_as_uint(Bs[buf][n][k8 + cq + 4]);
            }
            #pragma unroll
            for (int mt = 0; mt < 2; mt++)
                #pragma unroll
                for (int nt = 0; nt < NT; nt++)
                    mma_tf32(acc[mt][nt], a[mt], b[nt]);
        }
    }

    // Epilogue
    float* Cb = C + (size_t)zo * sCo + (size_t)zi * sCi;
    const float* Rb = RES ? (res + (size_t)zo * sCo + (size_t)zi * sCi) : nullptr;
    const int growb = blockIdx.y * BM + warpM * 32;
    const int gcolb = blockIdx.x * BN + warpN * WN;
    #pragma unroll
    for (int mt = 0; mt < 2; mt++) {
        #pragma unroll
        for (int half = 0; half < 2; half++) {
            const int row = growb + mt * 16 + half * 8 + r4;
            float* Crow = Cb + (size_t)row * ldc;
            const float* Rrow = RES ? (Rb + (size_t)row * ldc) : nullptr;
            #pragma unroll
            for (int nt = 0; nt < NT; nt++) {
                const int col = gcolb + nt * 8 + 2 * cq;
                float2 v;
                v.x = acc[mt][nt][half * 2 + 0];
                v.y = acc[mt][nt][half * 2 + 1];
                if (BIAS) {
                    v.x += bias[col]; v.y += bias[col + 1];
                }
                if (RES) {
                    v.x += Rrow[col]; v.y += Rrow[col + 1];
                }
                if (RELU) {
                    v.x = fmaxf(v.x, 0.f); v.y = fmaxf(v.y, 0.f);
                }
                *(float2*)(Crow + col) = v;
            }
        }
    }
}

// ---------------------------------------------------------------------------
// 32x32 tiled transpose with batched z-strides.  out[c][r] = in[r][c].
// ---------------------------------------------------------------------------
__global__ __launch_bounds__(256) void transpose32(
    const float* __restrict__ in, int ldin, long long sIi, long long sIo,
    float* __restrict__ out, int ldout, long long sOi, long long sOo, int zin)
{
    __shared__ float t[32][33];
    const int zi = (int)(blockIdx.z % zin), zo = (int)(blockIdx.z / zin);
    in  += (size_t)zo * sIo + (size_t)zi * sIi;
    out += (size_t)zo * sOo + (size_t)zi * sOi;
    const int c0 = blockIdx.x * 32, r0 = blockIdx.y * 32;
    const int tx = threadIdx.x & 31, ty = threadIdx.x >> 5;
    #pragma unroll
    for (int i = 0; i < 32; i += 8)
        t[ty + i][tx] = in[(size_t)(r0 + ty + i) * ldin + c0 + tx];
    __syncthreads();
    #pragma unroll
    for (int i = 0; i < 32; i += 8)
        out[(size_t)(c0 + ty + i) * ldout + r0 + tx] = t[tx][ty + i];
}

// ---------------------------------------------------------------------------
// Row softmax over S=2048 with 1/sqrt(HD)=0.125 scale, in place, normalized.
// ---------------------------------------------------------------------------
__global__ __launch_bounds__(256) void softmax_kernel(float* __restrict__ sm)
{
    float* p = sm + (size_t)blockIdx.x * S;
    const int t = threadIdx.x;
    float4 a = ((float4*)p)[t];
    float4 b = ((float4*)p)[t + 256];
    const float sc = 0.125f;
    a.x *= sc; a.y *= sc; a.z *= sc; a.w *= sc;
    b.x *= sc; b.y *= sc; b.z *= sc; b.w *= sc;

    float m = fmaxf(fmaxf(fmaxf(a.x, a.y), fmaxf(a.z, a.w)),
                    fmaxf(fmaxf(b.x, b.y), fmaxf(b.z, b.w)));
    __shared__ float red[256];
    red[t] = m; __syncthreads();
    #pragma unroll
    for (int st = 128; st > 0; st >>= 1) {
        if (t < st) red[t] = fmaxf(red[t], red[t + st]);
        __syncthreads();
    }
    m = red[0]; __syncthreads();

    a.x = __expf(a.x - m); a.y = __expf(a.y - m);
    a.z = __expf(a.z - m); a.w = __expf(a.w - m);
    b.x = __expf(b.x - m); b.y = __expf(b.y - m);
    b.z = __expf(b.z - m); b.w = __expf(b.w - m);
    float s8 = a.x + a.y + a.z + a.w + b.x + b.y + b.z + b.w;
    red[t] = s8; __syncthreads();
    #pragma unroll
    for (int st = 128; st > 0; st >>= 1) {
        if (t < st) red[t] += red[t + st];
        __syncthreads();
    }
    const float inv = 1.0f / red[0];
    a.x *= inv; a.y *= inv; a.z *= inv; a.w *= inv;
    b.x *= inv; b.y *= inv; b.z *= inv; b.w *= inv;
    ((float4*)p)[t] = a;
    ((float4*)p)[t + 256] = b;
}

// ---------------------------------------------------------------------------
// LayerNorm: one block per row (1024 floats), 256 threads, float4
// ---------------------------------------------------------------------------
__global__ __launch_bounds__(256) void ln_kernel(
    const float* __restrict__ x, const float* __restrict__ g,
    const float* __restrict__ b, float* __restrict__ y)
{
    int row = blockIdx.x;
    int t = threadIdx.x;
    float4 v = ((const float4*)(x + (size_t)row * DM))[t];
    float sum = v.x + v.y + v.z + v.w;
    float sq  = v.x*v.x + v.y*v.y + v.z*v.z + v.w*v.w;
    __shared__ float s1[256], s2[256];
    s1[t] = sum; s2[t] = sq;
    __syncthreads();
    #pragma unroll
    for (int st = 128; st > 0; st >>= 1) {
        if (t < st) { s1[t] += s1[t + st]; s2[t] += s2[t + st]; }
        __syncthreads();
    }
    float mu  = s1[0] * (1.0f / DM);
    float var = s2[0] * (1.0f / DM) - mu * mu;
    float inv = rsqrtf(var + LN_EPS);
    float4 gv = ((const float4*)g)[t];
    float4 bv = ((const float4*)b)[t];
    float4 o;
    o.x = (v.x - mu) * inv * gv.x + bv.x;
    o.y = (v.y - mu) * inv * gv.y + bv.y;
    o.z = (v.z - mu) * inv * gv.z + bv.z;
    o.w = (v.w - mu) * inv * gv.w + bv.w;
    ((float4*)(y + (size_t)row * DM))[t] = o;
}

// ---------------------------------------------------------------------------
// Launch
// ---------------------------------------------------------------------------
extern "C" void kernel_launch(void* const* d_in, const int* in_sizes, int n_in,
                              void* d_out, int out_size)
{
    const float* x    = (const float*)d_in[0];
    const float* w_q  = (const float*)d_in[2];
    const float* w_k  = (const float*)d_in[3];
    const float* w_v  = (const float*)d_in[4];
    const float* w_0  = (const float*)d_in[5];
    const float* b_0  = (const float*)d_in[6];
    const float* w_1  = (const float*)d_in[7];
    const float* b_1  = (const float*)d_in[8];
    const float* w_2  = (const float*)d_in[9];
    const float* b_2  = (const float*)d_in[10];
    const float* g_1  = (const float*)d_in[11];
    const float* be_1 = (const float*)d_in[12];
    const float* g_2  = (const float*)d_in[13];
    const float* be_2 = (const float*)d_in[14];
    float* out = (float*)d_out;

    float *xn, *q, *k, *v, *ao, *x2, *ff, *wqt, *wkt, *wvt, *w0t, *w1t, *w2t, *vt, *sg;
    cudaGetSymbolAddress((void**)&xn, g_xn);
    cudaGetSymbolAddress((void**)&q,  g_q);
    cudaGetSymbolAddress((void**)&k,  g_k);
    cudaGetSymbolAddress((void**)&v,  g_v);
    cudaGetSymbolAddress((void**)&ao, g_ao);
    cudaGetSymbolAddress((void**)&x2, g_x2);
    cudaGetSymbolAddress((void**)&ff, g_ff);
    cudaGetSymbolAddress((void**)&wqt, g_wqt);
    cudaGetSymbolAddress((void**)&wkt, g_wkt);
    cudaGetSymbolAddress((void**)&wvt, g_wvt);
    cudaGetSymbolAddress((void**)&w0t, g_w0t);
    cudaGetSymbolAddress((void**)&w1t, g_w1t);
    cudaGetSymbolAddress((void**)&w2t, g_w2t);
    cudaGetSymbolAddress((void**)&vt, g_vt);
    cudaGetSymbolAddress((void**)&sg, g_s);

    // Weight transposes: W[K][N] -> Wt[N][K]
    transpose32<<<dim3(DM/32,  DM/32,  1), 256>>>(w_q, DM, 0, 0, wqt, DM,  0, 0, 1);
    transpose32<<<dim3(DM/32,  DM/32,  1), 256>>>(w_k, DM, 0, 0, wkt, DM,  0, 0, 1);
    transpose32<<<dim3(DM/32,  DM/32,  1), 256>>>(w_v, DM, 0, 0, wvt, DM,  0, 0, 1);
    transpose32<<<dim3(DM/32,  DM/32,  1), 256>>>(w_0, DM, 0, 0, w0t, DM,  0, 0, 1);
    transpose32<<<dim3(DFF/32, DM/32,  1), 256>>>(w_1, DFF, 0, 0, w1t, DM, 0, 0, 1);
    transpose32<<<dim3(DM/32,  DFF/32, 1), 256>>>(w_2, DM, 0, 0, w2t, DFF, 0, 0, 1);

    // LN1
    ln_kernel<<<TOK, 256>>>(x, g_1, be_1, xn);

    // QKV projections
    mma_gemm<128,false,false,false><<<dim3(8, 32, 1), 256>>>(
        xn, DM, 0, 0, wqt, DM, 0, 0, q, DM, 0, 0, nullptr, nullptr, DM, 1);
    mma_gemm<128,false,false,false><<<dim3(8, 32, 1), 256>>>(
        xn, DM, 0, 0, wkt, DM, 0, 0, k, DM, 0, 0, nullptr, nullptr, DM, 1);
    mma_gemm<128,false,false,false><<<dim3(8, 32, 1), 256>>>(
        xn, DM, 0, 0, wvt, DM, 0, 0, v, DM, 0, 0, nullptr, nullptr, DM, 1);

    // V^T per (n,h): [kv][d] -> [d][kv]
    transpose32<<<dim3(HD/32, S/32, NB*NH), 256>>>(
        v, DM, HD, (long long)S*DM, vt, S, (long long)HD*S, 16LL*HD*S, NH);

    // scores[z][q][kv] = Q . K
    mma_gemm<128,false,false,false><<<dim3(S/128, S/128, NB*NH), 256>>>(
        q, DM, HD, (long long)S*DM,
        k, DM, HD, (long long)S*DM,
        sg, S, (long long)S*S, 16LL*S*S,
        nullptr, nullptr, HD, NH);

    // softmax rows (scale + normalize, in place)
    softmax_kernel<<<NB*NH*S, 256>>>(sg);

    // attn_out = P @ V   (B operand = V^T [d][kv] K-major)
    mma_gemm<64,false,false,false><<<dim3(1, S/128, NB*NH), 256>>>(
        sg, S, (long long)S*S, 16LL*S*S,
        vt, S, (long long)HD*S, 16LL*HD*S,
        ao, DM, HD, (long long)S*DM,
        nullptr, nullptr, S, NH);

    // x2 = x + ao @ W0 + b0
    mma_gemm<128,true,false,true><<<dim3(8, 32, 1), 256>>>(
        ao, DM, 0, 0, w0t, DM, 0, 0, x2, DM, 0, 0, b_0, x, DM, 1);

    // LN2
    ln_kernel<<<TOK, 256>>>(x2, g_2, be_2, xn);

    // ff = relu(xn @ W1 + b1)
    mma_gemm<128,true,true,false><<<dim3(DFF/128, 32, 1), 256>>>(
        xn, DM, 0, 0, w1t, DM, 0, 0, ff, DFF, 0, 0, b_1, nullptr, DM, 1);

    // out = x2 + ff @ W2 + b2
    mma_gemm<128,true,false,true><<<dim3(8, 32, 1), 256>>>(
        ff, DFF, 0, 0, w2t, DFF, 0, 0, out, DM, 0, 0, b_2, x2, DFF, 1);
}

// round 6
// speedup vs baseline: 2.1364x; 2.1364x over previous
#include <cuda_runtime.h>
#include <cuda_fp16.h>
#include <cstdint>
#include <math.h>

// ---------------------------------------------------------------------------
// Problem constants
// ---------------------------------------------------------------------------
#define NB   2
#define S    2048
#define DM   1024
#define NH   16
#define HD   64
#define DFF  4096
#define TOK  (NB * S)
#define LN_EPS 1e-5f

// ---------------------------------------------------------------------------
// Scratch (static device globals; no runtime allocation allowed)
// ---------------------------------------------------------------------------
__device__ __half g_xnh[(size_t)TOK * DM];
__device__ __half g_qh [(size_t)TOK * DM];
__device__ __half g_kh [(size_t)TOK * DM];
__device__ __half g_vh [(size_t)TOK * DM];
__device__ __half g_aoh[(size_t)TOK * DM];
__device__ __half g_ffh[(size_t)TOK * DFF];
__device__ float  g_x2 [(size_t)TOK * DM];
__device__ __half g_wqt[(size_t)DM * DM];
__device__ __half g_wkt[(size_t)DM * DM];
__device__ __half g_wvt[(size_t)DM * DM];
__device__ __half g_w0t[(size_t)DM * DM];
__device__ __half g_w1t[(size_t)DFF * DM];
__device__ __half g_w2t[(size_t)DM * DFF];

// ---------------------------------------------------------------------------
// Helpers
// ---------------------------------------------------------------------------
__device__ __forceinline__ void mma_f16(float* c, const uint32_t* a,
                                        uint32_t b0, uint32_t b1) {
    asm volatile(
        "mma.sync.aligned.m16n8k16.row.col.f32.f16.f16.f32 "
        "{%0,%1,%2,%3}, {%4,%5,%6,%7}, {%8,%9}, {%0,%1,%2,%3};"
        : "+f"(c[0]), "+f"(c[1]), "+f"(c[2]), "+f"(c[3])
        : "r"(a[0]), "r"(a[1]), "r"(a[2]), "r"(a[3]), "r"(b0), "r"(b1));
}
__device__ __forceinline__ uint32_t packh2(float x, float y) {
    __half2 h = __floats2half2_rn(x, y);
    return *(uint32_t*)&h;
}

// ---------------------------------------------------------------------------
// fp16 mma GEMM.  C[M,N] = A[M,K] @ B^T;  A fp16 [M][K], B fp16 [N][K].
// 128x128 tile, BK=32, 256 threads = 8 warps (4M x 2N), warp tile 32x64.
// Double-buffered smem [row][40] halves (conflict-free fragment loads),
// register-staged prefetch, 1 syncthreads per K-tile.
// ---------------------------------------------------------------------------
template<bool BIAS, bool RELU, bool RES, bool OUTH>
__global__ __launch_bounds__(256) void hgemm(
    const __half* __restrict__ A, int lda,
    const __half* __restrict__ B, int ldb,
    void* __restrict__ Cv, int ldc,
    const float* __restrict__ bias, const float* __restrict__ res, int K)
{
    constexpr int BM = 128, BN = 128, BK = 32, SK = 40;
    __shared__ __half As[2][BM][SK];
    __shared__ __half Bs[2][BN][SK];

    const int tid = threadIdx.x;
    const int wid = tid >> 5, lane = tid & 31;
    const int warpM = wid & 3, warpN = wid >> 2;
    const int g = lane >> 2, q4 = lane & 3;

    const __half* Ab = A + (size_t)blockIdx.y * BM * lda;
    const __half* Bb = B + (size_t)blockIdx.x * BN * ldb;

    // staging map: idx -> row = idx>>2, 8-half group = idx&3  (512 uint4 per tile)
    const int sr = tid >> 2, sc = tid & 3;

    float acc[2][8][4];
    #pragma unroll
    for (int mt = 0; mt < 2; mt++)
        #pragma unroll
        for (int nt = 0; nt < 8; nt++)
            #pragma unroll
            for (int j = 0; j < 4; j++) acc[mt][nt][j] = 0.0f;

    uint4 pa[2], pb[2];
    #pragma unroll
    for (int i = 0; i < 2; i++) {
        pa[i] = *(const uint4*)(Ab + (size_t)(sr + i * 64) * lda + sc * 8);
        pb[i] = *(const uint4*)(Bb + (size_t)(sr + i * 64) * ldb + sc * 8);
    }

    const int nit = K / BK;
    for (int t = 0; t < nit; t++) {
        const int buf = t & 1;
        #pragma unroll
        for (int i = 0; i < 2; i++) {
            *(uint4*)&As[buf][sr + i * 64][sc * 8] = pa[i];
            *(uint4*)&Bs[buf][sr + i * 64][sc * 8] = pb[i];
        }
        __syncthreads();

        if (t + 1 < nit) {
            const __half* Ak = Ab + (t + 1) * BK;
            const __half* Bk = Bb + (t + 1) * BK;
            #pragma unroll
            for (int i = 0; i < 2; i++) {
                pa[i] = *(const uint4*)(Ak + (size_t)(sr + i * 64) * lda + sc * 8);
                pb[i] = *(const uint4*)(Bk + (size_t)(sr + i * 64) * ldb + sc * 8);
            }
        }

        const int m0 = warpM * 32, n0 = warpN * 64;
        #pragma unroll
        for (int ks = 0; ks < 2; ks++) {
            const int kk = ks * 16 + 2 * q4;
            uint32_t a[2][4], b[8][2];
            #pragma unroll
            for (int mt = 0; mt < 2; mt++) {
                const int m = m0 + mt * 16 + g;
                a[mt][0] = *(const uint32_t*)&As[buf][m    ][kk];
                a[mt][1] = *(const uint32_t*)&As[buf][m + 8][kk];
                a[mt][2] = *(const uint32_t*)&As[buf][m    ][kk + 8];
                a[mt][3] = *(const uint32_t*)&As[buf][m + 8][kk + 8];
            }
            #pragma unroll
            for (int nt = 0; nt < 8; nt++) {
                const int n = n0 + nt * 8 + g;
                b[nt][0] = *(const uint32_t*)&Bs[buf][n][kk];
                b[nt][1] = *(const uint32_t*)&Bs[buf][n][kk + 8];
            }
            #pragma unroll
            for (int mt = 0; mt < 2; mt++)
                #pragma unroll
                for (int nt = 0; nt < 8; nt++)
                    mma_f16(acc[mt][nt], a[mt], b[nt][0], b[nt][1]);
        }
    }

    // Epilogue
    const int growb = blockIdx.y * BM + warpM * 32;
    const int gcolb = blockIdx.x * BN + warpN * 64;
    #pragma unroll
    for (int mt = 0; mt < 2; mt++) {
        #pragma unroll
        for (int half = 0; half < 2; half++) {
            const int row = growb + mt * 16 + half * 8 + g;
            #pragma unroll
            for (int nt = 0; nt < 8; nt++) {
                const int col = gcolb + nt * 8 + 2 * q4;
                float vx = acc[mt][nt][half * 2 + 0];
                float vy = acc[mt][nt][half * 2 + 1];
                if (BIAS) { vx += bias[col]; vy += bias[col + 1]; }
                if (RES) {
                    const float* rr = res + (size_t)row * ldc + col;
                    vx += rr[0]; vy += rr[1];
                }
                if (RELU) { vx = fmaxf(vx, 0.f); vy = fmaxf(vy, 0.f); }
                if (OUTH) {
                    *(uint32_t*)((__half*)Cv + (size_t)row * ldc + col) = packh2(vx, vy);
                } else {
                    *(float2*)((float*)Cv + (size_t)row * ldc + col) = make_float2(vx, vy);
                }
            }
        }
    }
}

// ---------------------------------------------------------------------------
// Flash attention, fp16 mma.  One block = 128 q rows for one (n,h).
// 8 warps x 16 rows; K/V tiles of 64 keys in smem (V transposed at load);
// online softmax; P fragments reinterpreted as A fragments of the PV mma.
// Q/K/V/O layout: [token = n*S+s][h*64+d], ld = 1024, fp16.
// ---------------------------------------------------------------------------
__global__ __launch_bounds__(256) void flash_attn(
    const __half* __restrict__ Qg, const __half* __restrict__ Kg,
    const __half* __restrict__ Vg, __half* __restrict__ Og)
{
    __shared__ __half Ksm[64][72];
    __shared__ __half Vt [64][72];

    const int tid = threadIdx.x, wid = tid >> 5, lane = tid & 31;
    const int g = lane >> 2, q4 = lane & 3;
    const int h = blockIdx.y, n = blockIdx.z;
    const int q0 = blockIdx.x * 128 + wid * 16;
    const size_t base = (size_t)n * S * DM + h * HD;

    // Q fragments (kept in registers for the whole kernel)
    uint32_t qf[4][4];
    {
        const __half* r0 = Qg + base + (size_t)(q0 + g) * DM;
        const __half* r1 = Qg + base + (size_t)(q0 + g + 8) * DM;
        #pragma unroll
        for (int ks = 0; ks < 4; ks++) {
            const int c = ks * 16 + 2 * q4;
            qf[ks][0] = *(const uint32_t*)(r0 + c);
            qf[ks][1] = *(const uint32_t*)(r1 + c);
            qf[ks][2] = *(const uint32_t*)(r0 + c + 8);
            qf[ks][3] = *(const uint32_t*)(r1 + c + 8);
        }
    }

    float o[8][4];
    #pragma unroll
    for (int nd = 0; nd < 8; nd++)
        #pragma unroll
        for (int j = 0; j < 4; j++) o[nd][j] = 0.0f;
    float m0 = -INFINITY, m1 = -INFINITY, l0 = 0.0f, l1 = 0.0f;

    for (int kv = 0; kv < S; kv += 64) {
        // Stage K and V^T tiles
        #pragma unroll
        for (int i = 0; i < 4; i++) {
            const int idx = tid + i * 256;          // 0..1023
            const int r = idx >> 4, cq = idx & 15;  // key row, 4-half group
            *(uint2*)&Ksm[r][cq * 4] =
                *(const uint2*)(Kg + base + (size_t)(kv + r) * DM + cq * 4);
            __half vv[4];
            *(uint2*)vv = *(const uint2*)(Vg + base + (size_t)(kv + r) * DM + cq * 4);
            Vt[cq * 4 + 0][r] = vv[0];
            Vt[cq * 4 + 1][r] = vv[1];
            Vt[cq * 4 + 2][r] = vv[2];
            Vt[cq * 4 + 3][r] = vv[3];
        }
        __syncthreads();

        // S = Q @ K^T  (raw scores; 0.125 scale folded into exp)
        float c[8][4];
        #pragma unroll
        for (int nt = 0; nt < 8; nt++)
            #pragma unroll
            for (int j = 0; j < 4; j++) c[nt][j] = 0.0f;
        #pragma unroll
        for (int ks = 0; ks < 4; ks++) {
            const int kk = ks * 16 + 2 * q4;
            #pragma unroll
            for (int nt = 0; nt < 8; nt++) {
                const uint32_t b0 = *(const uint32_t*)&Ksm[nt * 8 + g][kk];
                const uint32_t b1 = *(const uint32_t*)&Ksm[nt * 8 + g][kk + 8];
                mma_f16(c[nt], qf[ks], b0, b1);
            }
        }

        // Online softmax
        float mx0 = -INFINITY, mx1 = -INFINITY;
        #pragma unroll
        for (int nt = 0; nt < 8; nt++) {
            mx0 = fmaxf(mx0, fmaxf(c[nt][0], c[nt][1]));
            mx1 = fmaxf(mx1, fmaxf(c[nt][2], c[nt][3]));
        }
        mx0 = fmaxf(mx0, __shfl_xor_sync(0xffffffffu, mx0, 1));
        mx0 = fmaxf(mx0, __shfl_xor_sync(0xffffffffu, mx0, 2));
        mx1 = fmaxf(mx1, __shfl_xor_sync(0xffffffffu, mx1, 1));
        mx1 = fmaxf(mx1, __shfl_xor_sync(0xffffffffu, mx1, 2));
        const float nm0 = fmaxf(m0, mx0), nm1 = fmaxf(m1, mx1);
        const float r0 = __expf((m0 - nm0) * 0.125f);
        const float r1 = __expf((m1 - nm1) * 0.125f);
        m0 = nm0; m1 = nm1;

        float s0 = 0.0f, s1 = 0.0f;
        #pragma unroll
        for (int nt = 0; nt < 8; nt++) {
            c[nt][0] = __expf((c[nt][0] - m0) * 0.125f);
            c[nt][1] = __expf((c[nt][1] - m0) * 0.125f);
            c[nt][2] = __expf((c[nt][2] - m1) * 0.125f);
            c[nt][3] = __expf((c[nt][3] - m1) * 0.125f);
            s0 += c[nt][0] + c[nt][1];
            s1 += c[nt][2] + c[nt][3];
        }
        s0 += __shfl_xor_sync(0xffffffffu, s0, 1);
        s0 += __shfl_xor_sync(0xffffffffu, s0, 2);
        s1 += __shfl_xor_sync(0xffffffffu, s1, 1);
        s1 += __shfl_xor_sync(0xffffffffu, s1, 2);
        l0 = l0 * r0 + s0;
        l1 = l1 * r1 + s1;

        #pragma unroll
        for (int nd = 0; nd < 8; nd++) {
            o[nd][0] *= r0; o[nd][1] *= r0;
            o[nd][2] *= r1; o[nd][3] *= r1;
        }

        // O += P @ V  (P fragments built from the S accumulator)
        #pragma unroll
        for (int ks2 = 0; ks2 < 4; ks2++) {
            uint32_t pa[4];
            pa[0] = packh2(c[2 * ks2][0],     c[2 * ks2][1]);
            pa[1] = packh2(c[2 * ks2][2],     c[2 * ks2][3]);
            pa[2] = packh2(c[2 * ks2 + 1][0], c[2 * ks2 + 1][1]);
            pa[3] = packh2(c[2 * ks2 + 1][2], c[2 * ks2 + 1][3]);
            const int kk = ks2 * 16 + 2 * q4;
            #pragma unroll
            for (int nd = 0; nd < 8; nd++) {
                const uint32_t b0 = *(const uint32_t*)&Vt[nd * 8 + g][kk];
                const uint32_t b1 = *(const uint32_t*)&Vt[nd * 8 + g][kk + 8];
                mma_f16(o[nd], pa, b0, b1);
            }
        }
        __syncthreads();
    }

    const float i0 = 1.0f / l0, i1 = 1.0f / l1;
    __half* o0 = Og + base + (size_t)(q0 + g) * DM;
    __half* o1 = Og + base + (size_t)(q0 + g + 8) * DM;
    #pragma unroll
    for (int nd = 0; nd < 8; nd++) {
        const int col = nd * 8 + 2 * q4;
        *(uint32_t*)(o0 + col) = packh2(o[nd][0] * i0, o[nd][1] * i0);
        *(uint32_t*)(o1 + col) = packh2(o[nd][2] * i1, o[nd][3] * i1);
    }
}

// ---------------------------------------------------------------------------
// Transpose fp32 [rows][cols] -> fp16 [cols][rows]
// ---------------------------------------------------------------------------
__global__ __launch_bounds__(256) void transpose_h(
    const float* __restrict__ in, int rows, int cols, __half* __restrict__ out)
{
    __shared__ float t[32][33];
    const int c0 = blockIdx.x * 32, r0 = blockIdx.y * 32;
    const int tx = threadIdx.x & 31, ty = threadIdx.x >> 5;
    #pragma unroll
    for (int i = 0; i < 32; i += 8)
        t[ty + i][tx] = in[(size_t)(r0 + ty + i) * cols + c0 + tx];
    __syncthreads();
    #pragma unroll
    for (int i = 0; i < 32; i += 8)
        out[(size_t)(c0 + ty + i) * rows + r0 + tx] = __float2half(t[tx][ty + i]);
}

// ---------------------------------------------------------------------------
// LayerNorm fp32 in -> fp16 out.  One block per row, 256 threads, float4.
// ---------------------------------------------------------------------------
__global__ __launch_bounds__(256) void ln_h(
    const float* __restrict__ x, const float* __restrict__ g,
    const float* __restrict__ b, __half* __restrict__ y)
{
    const int row = blockIdx.x, t = threadIdx.x;
    float4 v = ((const float4*)(x + (size_t)row * DM))[t];
    float sum = v.x + v.y + v.z + v.w;
    float sq  = v.x*v.x + v.y*v.y + v.z*v.z + v.w*v.w;
    __shared__ float s1[256], s2[256];
    s1[t] = sum; s2[t] = sq;
    __syncthreads();
    #pragma unroll
    for (int st = 128; st > 0; st >>= 1) {
        if (t < st) { s1[t] += s1[t + st]; s2[t] += s2[t + st]; }
        __syncthreads();
    }
    const float mu  = s1[0] * (1.0f / DM);
    const float var = s2[0] * (1.0f / DM) - mu * mu;
    const float inv = rsqrtf(var + LN_EPS);
    const float4 gv = ((const float4*)g)[t];
    const float4 bv = ((const float4*)b)[t];
    uint2 ov;
    ov.x = packh2((v.x - mu) * inv * gv.x + bv.x, (v.y - mu) * inv * gv.y + bv.y);
    ov.y = packh2((v.z - mu) * inv * gv.z + bv.z, (v.w - mu) * inv * gv.w + bv.w);
    ((uint2*)(y + (size_t)row * DM))[t] = ov;
}

// ---------------------------------------------------------------------------
// Launch
// ---------------------------------------------------------------------------
extern "C" void kernel_launch(void* const* d_in, const int* in_sizes, int n_in,
                              void* d_out, int out_size)
{
    const float* x    = (const float*)d_in[0];
    const float* w_q  = (const float*)d_in[2];
    const float* w_k  = (const float*)d_in[3];
    const float* w_v  = (const float*)d_in[4];
    const float* w_0  = (const float*)d_in[5];
    const float* b_0  = (const float*)d_in[6];
    const float* w_1  = (const float*)d_in[7];
    const float* b_1  = (const float*)d_in[8];
    const float* w_2  = (const float*)d_in[9];
    const float* b_2  = (const float*)d_in[10];
    const float* g_1  = (const float*)d_in[11];
    const float* be_1 = (const float*)d_in[12];
    const float* g_2  = (const float*)d_in[13];
    const float* be_2 = (const float*)d_in[14];
    float* out = (float*)d_out;

    __half *xnh, *qh, *kh, *vh, *aoh, *ffh, *wqt, *wkt, *wvt, *w0t, *w1t, *w2t;
    float* x2;
    cudaGetSymbolAddress((void**)&xnh, g_xnh);
    cudaGetSymbolAddress((void**)&qh,  g_qh);
    cudaGetSymbolAddress((void**)&kh,  g_kh);
    cudaGetSymbolAddress((void**)&vh,  g_vh);
    cudaGetSymbolAddress((void**)&aoh, g_aoh);
    cudaGetSymbolAddress((void**)&ffh, g_ffh);
    cudaGetSymbolAddress((void**)&x2,  g_x2);
    cudaGetSymbolAddress((void**)&wqt, g_wqt);
    cudaGetSymbolAddress((void**)&wkt, g_wkt);
    cudaGetSymbolAddress((void**)&wvt, g_wvt);
    cudaGetSymbolAddress((void**)&w0t, g_w0t);
    cudaGetSymbolAddress((void**)&w1t, g_w1t);
    cudaGetSymbolAddress((void**)&w2t, g_w2t);

    // Weight transpose+convert: W[K][N] fp32 -> Wt[N][K] fp16
    transpose_h<<<dim3(DM/32,  DM/32),  256>>>(w_q, DM, DM, wqt);
    transpose_h<<<dim3(DM/32,  DM/32),  256>>>(w_k, DM, DM, wkt);
    transpose_h<<<dim3(DM/32,  DM/32),  256>>>(w_v, DM, DM, wvt);
    transpose_h<<<dim3(DM/32,  DM/32),  256>>>(w_0, DM, DM, w0t);
    transpose_h<<<dim3(DFF/32, DM/32),  256>>>(w_1, DM, DFF, w1t);
    transpose_h<<<dim3(DM/32,  DFF/32), 256>>>(w_2, DFF, DM, w2t);

    // LN1 -> fp16
    ln_h<<<TOK, 256>>>(x, g_1, be_1, xnh);

    // QKV projections (fp16 out)
    hgemm<false,false,false,true><<<dim3(8, 32), 256>>>(xnh, DM, wqt, DM, qh, DM, nullptr, nullptr, DM);
    hgemm<false,false,false,true><<<dim3(8, 32), 256>>>(xnh, DM, wkt, DM, kh, DM, nullptr, nullptr, DM);
    hgemm<false,false,false,true><<<dim3(8, 32), 256>>>(xnh, DM, wvt, DM, vh, DM, nullptr, nullptr, DM);

    // Fused attention
    flash_attn<<<dim3(S/128, NH, NB), 256>>>(qh, kh, vh, aoh);

    // x2 = x + ao @ W0 + b0   (fp32 out)
    hgemm<true,false,true,false><<<dim3(8, 32), 256>>>(aoh, DM, w0t, DM, x2, DM, b_0, x, DM);

    // LN2 -> fp16
    ln_h<<<TOK, 256>>>(x2, g_2, be_2, xnh);

    // ff = relu(xn @ W1 + b1)  (fp16 out)
    hgemm<true,true,false,true><<<dim3(32, 32), 256>>>(xnh, DM, w1t, DM, ffh, DFF, b_1, nullptr, DM);

    // out = x2 + ff @ W2 + b2  (fp32 out)
    hgemm<true,false,true,false><<<dim3(8, 32), 256>>>(ffh, DFF, w2t, DFF, out, DM, b_2, x2, DFF);
}

// round 7
// speedup vs baseline: 2.1364x; 1.0000x over previous
#include <cuda_runtime.h>
#include <cuda_fp16.h>
#include <cstdint>
#include <math.h>

// ---------------------------------------------------------------------------
// Problem constants
// ---------------------------------------------------------------------------
#define NB   2
#define S    2048
#define DM   1024
#define NH   16
#define HD   64
#define DFF  4096
#define TOK  (NB * S)
#define LN_EPS 1e-5f

// ---------------------------------------------------------------------------
// Scratch (static device globals; no runtime allocation allowed)
// ---------------------------------------------------------------------------
__device__ __half g_xnh[(size_t)TOK * DM];
__device__ __half g_qh [(size_t)TOK * DM];
__device__ __half g_kh [(size_t)TOK * DM];
__device__ __half g_vh [(size_t)TOK * DM];
__device__ __half g_aoh[(size_t)TOK * DM];
__device__ __half g_ffh[(size_t)TOK * DFF];
__device__ float  g_x2 [(size_t)TOK * DM];
__device__ __half g_wqt[(size_t)DM * DM];
__device__ __half g_wkt[(size_t)DM * DM];
__device__ __half g_wvt[(size_t)DM * DM];
__device__ __half g_w0t[(size_t)DM * DM];
__device__ __half g_w1t[(size_t)DFF * DM];
__device__ __half g_w2t[(size_t)DM * DFF];

// ---------------------------------------------------------------------------
// Helpers
// ---------------------------------------------------------------------------
__device__ __forceinline__ void mma_f16(float* c, const uint32_t* a,
                                        uint32_t b0, uint32_t b1) {
    asm volatile(
        "mma.sync.aligned.m16n8k16.row.col.f32.f16.f16.f32 "
        "{%0,%1,%2,%3}, {%4,%5,%6,%7}, {%8,%9}, {%0,%1,%2,%3};"
        : "+f"(c[0]), "+f"(c[1]), "+f"(c[2]), "+f"(c[3])
        : "r"(a[0]), "r"(a[1]), "r"(a[2]), "r"(a[3]), "r"(b0), "r"(b1));
}
__device__ __forceinline__ uint32_t packh2(float x, float y) {
    __half2 h = __floats2half2_rn(x, y);
    return *(uint32_t*)&h;
}

// ---------------------------------------------------------------------------
// fp16 mma GEMM.  C[M,N] = A[M,K] @ B^T;  A fp16 [M][K], B fp16 [N][K].
// 128x128 tile, BK=32, 256 threads = 8 warps (4M x 2N), warp tile 32x64.
// Double-buffered smem [row][40] halves (conflict-free fragment loads),
// register-staged prefetch, 1 syncthreads per K-tile.
// ---------------------------------------------------------------------------
template<bool BIAS, bool RELU, bool RES, bool OUTH>
__global__ __launch_bounds__(256) void hgemm(
    const __half* __restrict__ A, int lda,
    const __half* __restrict__ B, int ldb,
    void* __restrict__ Cv, int ldc,
    const float* __restrict__ bias, const float* __restrict__ res, int K)
{
    constexpr int BM = 128, BN = 128, BK = 32, SK = 40;
    __shared__ __half As[2][BM][SK];
    __shared__ __half Bs[2][BN][SK];

    const int tid = threadIdx.x;
    const int wid = tid >> 5, lane = tid & 31;
    const int warpM = wid & 3, warpN = wid >> 2;
    const int g = lane >> 2, q4 = lane & 3;

    const __half* Ab = A + (size_t)blockIdx.y * BM * lda;
    const __half* Bb = B + (size_t)blockIdx.x * BN * ldb;

    // staging map: idx -> row = idx>>2, 8-half group = idx&3  (512 uint4 per tile)
    const int sr = tid >> 2, sc = tid & 3;

    float acc[2][8][4];
    #pragma unroll
    for (int mt = 0; mt < 2; mt++)
        #pragma unroll
        for (int nt = 0; nt < 8; nt++)
            #pragma unroll
            for (int j = 0; j < 4; j++) acc[mt][nt][j] = 0.0f;

    uint4 pa[2], pb[2];
    #pragma unroll
    for (int i = 0; i < 2; i++) {
        pa[i] = *(const uint4*)(Ab + (size_t)(sr + i * 64) * lda + sc * 8);
        pb[i] = *(const uint4*)(Bb + (size_t)(sr + i * 64) * ldb + sc * 8);
    }

    const int nit = K / BK;
    for (int t = 0; t < nit; t++) {
        const int buf = t & 1;
        #pragma unroll
        for (int i = 0; i < 2; i++) {
            *(uint4*)&As[buf][sr + i * 64][sc * 8] = pa[i];
            *(uint4*)&Bs[buf][sr + i * 64][sc * 8] = pb[i];
        }
        __syncthreads();

        if (t + 1 < nit) {
            const __half* Ak = Ab + (t + 1) * BK;
            const __half* Bk = Bb + (t + 1) * BK;
            #pragma unroll
            for (int i = 0; i < 2; i++) {
                pa[i] = *(const uint4*)(Ak + (size_t)(sr + i * 64) * lda + sc * 8);
                pb[i] = *(const uint4*)(Bk + (size_t)(sr + i * 64) * ldb + sc * 8);
            }
        }

        const int m0 = warpM * 32, n0 = warpN * 64;
        #pragma unroll
        for (int ks = 0; ks < 2; ks++) {
            const int kk = ks * 16 + 2 * q4;
            uint32_t a[2][4], b[8][2];
            #pragma unroll
            for (int mt = 0; mt < 2; mt++) {
                const int m = m0 + mt * 16 + g;
                a[mt][0] = *(const uint32_t*)&As[buf][m    ][kk];
                a[mt][1] = *(const uint32_t*)&As[buf][m + 8][kk];
                a[mt][2] = *(const uint32_t*)&As[buf][m    ][kk + 8];
                a[mt][3] = *(const uint32_t*)&As[buf][m + 8][kk + 8];
            }
            #pragma unroll
            for (int nt = 0; nt < 8; nt++) {
                const int n = n0 + nt * 8 + g;
                b[nt][0] = *(const uint32_t*)&Bs[buf][n][kk];
                b[nt][1] = *(const uint32_t*)&Bs[buf][n][kk + 8];
            }
            #pragma unroll
            for (int mt = 0; mt < 2; mt++)
                #pragma unroll
                for (int nt = 0; nt < 8; nt++)
                    mma_f16(acc[mt][nt], a[mt], b[nt][0], b[nt][1]);
        }
    }

    // Epilogue
    const int growb = blockIdx.y * BM + warpM * 32;
    const int gcolb = blockIdx.x * BN + warpN * 64;
    #pragma unroll
    for (int mt = 0; mt < 2; mt++) {
        #pragma unroll
        for (int half = 0; half < 2; half++) {
            const int row = growb + mt * 16 + half * 8 + g;
            #pragma unroll
            for (int nt = 0; nt < 8; nt++) {
                const int col = gcolb + nt * 8 + 2 * q4;
                float vx = acc[mt][nt][half * 2 + 0];
                float vy = acc[mt][nt][half * 2 + 1];
                if (BIAS) { vx += bias[col]; vy += bias[col + 1]; }
                if (RES) {
                    const float* rr = res + (size_t)row * ldc + col;
                    vx += rr[0]; vy += rr[1];
                }
                if (RELU) { vx = fmaxf(vx, 0.f); vy = fmaxf(vy, 0.f); }
                if (OUTH) {
                    *(uint32_t*)((__half*)Cv + (size_t)row * ldc + col) = packh2(vx, vy);
                } else {
                    *(float2*)((float*)Cv + (size_t)row * ldc + col) = make_float2(vx, vy);
                }
            }
        }
    }
}

// ---------------------------------------------------------------------------
// Flash attention, fp16 mma.  One block = 128 q rows for one (n,h).
// 8 warps x 16 rows; K/V tiles of 64 keys in smem (V transposed at load);
// online softmax; P fragments reinterpreted as A fragments of the PV mma.
// Q/K/V/O layout: [token = n*S+s][h*64+d], ld = 1024, fp16.
// ---------------------------------------------------------------------------
__global__ __launch_bounds__(256) void flash_attn(
    const __half* __restrict__ Qg, const __half* __restrict__ Kg,
    const __half* __restrict__ Vg, __half* __restrict__ Og)
{
    __shared__ __half Ksm[64][72];
    __shared__ __half Vt [64][72];

    const int tid = threadIdx.x, wid = tid >> 5, lane = tid & 31;
    const int g = lane >> 2, q4 = lane & 3;
    const int h = blockIdx.y, n = blockIdx.z;
    const int q0 = blockIdx.x * 128 + wid * 16;
    const size_t base = (size_t)n * S * DM + h * HD;

    // Q fragments (kept in registers for the whole kernel)
    uint32_t qf[4][4];
    {
        const __half* r0 = Qg + base + (size_t)(q0 + g) * DM;
        const __half* r1 = Qg + base + (size_t)(q0 + g + 8) * DM;
        #pragma unroll
        for (int ks = 0; ks < 4; ks++) {
            const int c = ks * 16 + 2 * q4;
            qf[ks][0] = *(const uint32_t*)(r0 + c);
            qf[ks][1] = *(const uint32_t*)(r1 + c);
            qf[ks][2] = *(const uint32_t*)(r0 + c + 8);
            qf[ks][3] = *(const uint32_t*)(r1 + c + 8);
        }
    }

    float o[8][4];
    #pragma unroll
    for (int nd = 0; nd < 8; nd++)
        #pragma unroll
        for (int j = 0; j < 4; j++) o[nd][j] = 0.0f;
    float m0 = -INFINITY, m1 = -INFINITY, l0 = 0.0f, l1 = 0.0f;

    for (int kv = 0; kv < S; kv += 64) {
        // Stage K and V^T tiles
        #pragma unroll
        for (int i = 0; i < 4; i++) {
            const int idx = tid + i * 256;          // 0..1023
            const int r = idx >> 4, cq = idx & 15;  // key row, 4-half group
            *(uint2*)&Ksm[r][cq * 4] =
                *(const uint2*)(Kg + base + (size_t)(kv + r) * DM + cq * 4);
            __half vv[4];
            *(uint2*)vv = *(const uint2*)(Vg + base + (size_t)(kv + r) * DM + cq * 4);
            Vt[cq * 4 + 0][r] = vv[0];
            Vt[cq * 4 + 1][r] = vv[1];
            Vt[cq * 4 + 2][r] = vv[2];
            Vt[cq * 4 + 3][r] = vv[3];
        }
        __syncthreads();

        // S = Q @ K^T  (raw scores; 0.125 scale folded into exp)
        float c[8][4];
        #pragma unroll
        for (int nt = 0; nt < 8; nt++)
            #pragma unroll
            for (int j = 0; j < 4; j++) c[nt][j] = 0.0f;
        #pragma unroll
        for (int ks = 0; ks < 4; ks++) {
            const int kk = ks * 16 + 2 * q4;
            #pragma unroll
            for (int nt = 0; nt < 8; nt++) {
                const uint32_t b0 = *(const uint32_t*)&Ksm[nt * 8 + g][kk];
                const uint32_t b1 = *(const uint32_t*)&Ksm[nt * 8 + g][kk + 8];
                mma_f16(c[nt], qf[ks], b0, b1);
            }
        }

        // Online softmax
        float mx0 = -INFINITY, mx1 = -INFINITY;
        #pragma unroll
        for (int nt = 0; nt < 8; nt++) {
            mx0 = fmaxf(mx0, fmaxf(c[nt][0], c[nt][1]));
            mx1 = fmaxf(mx1, fmaxf(c[nt][2], c[nt][3]));
        }
        mx0 = fmaxf(mx0, __shfl_xor_sync(0xffffffffu, mx0, 1));
        mx0 = fmaxf(mx0, __shfl_xor_sync(0xffffffffu, mx0, 2));
        mx1 = fmaxf(mx1, __shfl_xor_sync(0xffffffffu, mx1, 1));
        mx1 = fmaxf(mx1, __shfl_xor_sync(0xffffffffu, mx1, 2));
        const float nm0 = fmaxf(m0, mx0), nm1 = fmaxf(m1, mx1);
        const float r0 = __expf((m0 - nm0) * 0.125f);
        const float r1 = __expf((m1 - nm1) * 0.125f);
        m0 = nm0; m1 = nm1;

        float s0 = 0.0f, s1 = 0.0f;
        #pragma unroll
        for (int nt = 0; nt < 8; nt++) {
            c[nt][0] = __expf((c[nt][0] - m0) * 0.125f);
            c[nt][1] = __expf((c[nt][1] - m0) * 0.125f);
            c[nt][2] = __expf((c[nt][2] - m1) * 0.125f);
            c[nt][3] = __expf((c[nt][3] - m1) * 0.125f);
            s0 += c[nt][0] + c[nt][1];
            s1 += c[nt][2] + c[nt][3];
        }
        s0 += __shfl_xor_sync(0xffffffffu, s0, 1);
        s0 += __shfl_xor_sync(0xffffffffu, s0, 2);
        s1 += __shfl_xor_sync(0xffffffffu, s1, 1);
        s1 += __shfl_xor_sync(0xffffffffu, s1, 2);
        l0 = l0 * r0 + s0;
        l1 = l1 * r1 + s1;

        #pragma unroll
        for (int nd = 0; nd < 8; nd++) {
            o[nd][0] *= r0; o[nd][1] *= r0;
            o[nd][2] *= r1; o[nd][3] *= r1;
        }

        // O += P @ V  (P fragments built from the S accumulator)
        #pragma unroll
        for (int ks2 = 0; ks2 < 4; ks2++) {
            uint32_t pa[4];
            pa[0] = packh2(c[2 * ks2][0],     c[2 * ks2][1]);
            pa[1] = packh2(c[2 * ks2][2],     c[2 * ks2][3]);
            pa[2] = packh2(c[2 * ks2 + 1][0], c[2 * ks2 + 1][1]);
            pa[3] = packh2(c[2 * ks2 + 1][2], c[2 * ks2 + 1][3]);
            const int kk = ks2 * 16 + 2 * q4;
            #pragma unroll
            for (int nd = 0; nd < 8; nd++) {
                const uint32_t b0 = *(const uint32_t*)&Vt[nd * 8 + g][kk];
                const uint32_t b1 = *(const uint32_t*)&Vt[nd * 8 + g][kk + 8];
                mma_f16(o[nd], pa, b0, b1);
            }
        }
        __syncthreads();
    }

    const float i0 = 1.0f / l0, i1 = 1.0f / l1;
    __half* o0 = Og + base + (size_t)(q0 + g) * DM;
    __half* o1 = Og + base + (size_t)(q0 + g + 8) * DM;
    #pragma unroll
    for (int nd = 0; nd < 8; nd++) {
        const int col = nd * 8 + 2 * q4;
        *(uint32_t*)(o0 + col) = packh2(o[nd][0] * i0, o[nd][1] * i0);
        *(uint32_t*)(o1 + col) = packh2(o[nd][2] * i1, o[nd][3] * i1);
    }
}

// ---------------------------------------------------------------------------
// Transpose fp32 [rows][cols] -> fp16 [cols][rows]
// ---------------------------------------------------------------------------
__global__ __launch_bounds__(256) void transpose_h(
    const float* __restrict__ in, int rows, int cols, __half* __restrict__ out)
{
    __shared__ float t[32][33];
    const int c0 = blockIdx.x * 32, r0 = blockIdx.y * 32;
    const int tx = threadIdx.x & 31, ty = threadIdx.x >> 5;
    #pragma unroll
    for (int i = 0; i < 32; i += 8)
        t[ty + i][tx] = in[(size_t)(r0 + ty + i) * cols + c0 + tx];
    __syncthreads();
    #pragma unroll
    for (int i = 0; i < 32; i += 8)
        out[(size_t)(c0 + ty + i) * rows + r0 + tx] = __float2half(t[tx][ty + i]);
}

// ---------------------------------------------------------------------------
// LayerNorm fp32 in -> fp16 out.  One block per row, 256 threads, float4.
// ---------------------------------------------------------------------------
__global__ __launch_bounds__(256) void ln_h(
    const float* __restrict__ x, const float* __restrict__ g,
    const float* __restrict__ b, __half* __restrict__ y)
{
    const int row = blockIdx.x, t = threadIdx.x;
    float4 v = ((const float4*)(x + (size_t)row * DM))[t];
    float sum = v.x + v.y + v.z + v.w;
    float sq  = v.x*v.x + v.y*v.y + v.z*v.z + v.w*v.w;
    __shared__ float s1[256], s2[256];
    s1[t] = sum; s2[t] = sq;
    __syncthreads();
    #pragma unroll
    for (int st = 128; st > 0; st >>= 1) {
        if (t < st) { s1[t] += s1[t + st]; s2[t] += s2[t + st]; }
        __syncthreads();
    }
    const float mu  = s1[0] * (1.0f / DM);
    const float var = s2[0] * (1.0f / DM) - mu * mu;
    const float inv = rsqrtf(var + LN_EPS);
    const float4 gv = ((const float4*)g)[t];
    const float4 bv = ((const float4*)b)[t];
    uint2 ov;
    ov.x = packh2((v.x - mu) * inv * gv.x + bv.x, (v.y - mu) * inv * gv.y + bv.y);
    ov.y = packh2((v.z - mu) * inv * gv.z + bv.z, (v.w - mu) * inv * gv.w + bv.w);
    ((uint2*)(y + (size_t)row * DM))[t] = ov;
}

// ---------------------------------------------------------------------------
// Launch
// ---------------------------------------------------------------------------
extern "C" void kernel_launch(void* const* d_in, const int* in_sizes, int n_in,
                              void* d_out, int out_size)
{
    const float* x    = (const float*)d_in[0];
    const float* w_q  = (const float*)d_in[2];
    const float* w_k  = (const float*)d_in[3];
    const float* w_v  = (const float*)d_in[4];
    const float* w_0  = (const float*)d_in[5];
    const float* b_0  = (const float*)d_in[6];
    const float* w_1  = (const float*)d_in[7];
    const float* b_1  = (const float*)d_in[8];
    const float* w_2  = (const float*)d_in[9];
    const float* b_2  = (const float*)d_in[10];
    const float* g_1  = (const float*)d_in[11];
    const float* be_1 = (const float*)d_in[12];
    const float* g_2  = (const float*)d_in[13];
    const float* be_2 = (const float*)d_in[14];
    float* out = (float*)d_out;

    __half *xnh, *qh, *kh, *vh, *aoh, *ffh, *wqt, *wkt, *wvt, *w0t, *w1t, *w2t;
    float* x2;
    cudaGetSymbolAddress((void**)&xnh, g_xnh);
    cudaGetSymbolAddress((void**)&qh,  g_qh);
    cudaGetSymbolAddress((void**)&kh,  g_kh);
    cudaGetSymbolAddress((void**)&vh,  g_vh);
    cudaGetSymbolAddress((void**)&aoh, g_aoh);
    cudaGetSymbolAddress((void**)&ffh, g_ffh);
    cudaGetSymbolAddress((void**)&x2,  g_x2);
    cudaGetSymbolAddress((void**)&wqt, g_wqt);
    cudaGetSymbolAddress((void**)&wkt, g_wkt);
    cudaGetSymbolAddress((void**)&wvt, g_wvt);
    cudaGetSymbolAddress((void**)&w0t, g_w0t);
    cudaGetSymbolAddress((void**)&w1t, g_w1t);
    cudaGetSymbolAddress((void**)&w2t, g_w2t);

    // Weight transpose+convert: W[K][N] fp32 -> Wt[N][K] fp16
    transpose_h<<<dim3(DM/32,  DM/32),  256>>>(w_q, DM, DM, wqt);
    transpose_h<<<dim3(DM/32,  DM/32),  256>>>(w_k, DM, DM, wkt);
    transpose_h<<<dim3(DM/32,  DM/32),  256>>>(w_v, DM, DM, wvt);
    transpose_h<<<dim3(DM/32,  DM/32),  256>>>(w_0, DM, DM, w0t);
    transpose_h<<<dim3(DFF/32, DM/32),  256>>>(w_1, DM, DFF, w1t);
    transpose_h<<<dim3(DM/32,  DFF/32), 256>>>(w_2, DFF, DM, w2t);

    // LN1 -> fp16
    ln_h<<<TOK, 256>>>(x, g_1, be_1, xnh);

    // QKV projections (fp16 out)
    hgemm<false,false,false,true><<<dim3(8, 32), 256>>>(xnh, DM, wqt, DM, qh, DM, nullptr, nullptr, DM);
    hgemm<false,false,false,true><<<dim3(8, 32), 256>>>(xnh, DM, wkt, DM, kh, DM, nullptr, nullptr, DM);
    hgemm<false,false,false,true><<<dim3(8, 32), 256>>>(xnh, DM, wvt, DM, vh, DM, nullptr, nullptr, DM);

    // Fused attention
    flash_attn<<<dim3(S/128, NH, NB), 256>>>(qh, kh, vh, aoh);

    // x2 = x + ao @ W0 + b0   (fp32 out)
    hgemm<true,false,true,false><<<dim3(8, 32), 256>>>(aoh, DM, w0t, DM, x2, DM, b_0, x, DM);

    // LN2 -> fp16
    ln_h<<<TOK, 256>>>(x2, g_2, be_2, xnh);

    // ff = relu(xn @ W1 + b1)  (fp16 out)
    hgemm<true,true,false,true><<<dim3(32, 32), 256>>>(xnh, DM, w1t, DM, ffh, DFF, b_1, nullptr, DM);

    // out = x2 + ff @ W2 + b2  (fp32 out)
    hgemm<true,false,true,false><<<dim3(8, 32), 256>>>(ffh, DFF, w2t, DFF, out, DM, b_2, x2, DFF);
}

// round 8
// speedup vs baseline: 2.4792x; 1.1604x over previous
#include <cuda_runtime.h>
#include <cuda_fp16.h>
#include <cstdint>
#include <math.h>

// ---------------------------------------------------------------------------
// Problem constants
// ---------------------------------------------------------------------------
#define NB   2
#define S    2048
#define DM   1024
#define NH   16
#define HD   64
#define DFF  4096
#define TOK  (NB * S)
#define LN_EPS 1e-5f

// ---------------------------------------------------------------------------
// Scratch (static device globals; no runtime allocation allowed)
// ---------------------------------------------------------------------------
__device__ __half g_xnh [(size_t)TOK * DM];
__device__ __half g_qkv [(size_t)TOK * 3 * DM];   // packed Q|K|V, ld = 3072
__device__ __half g_aoh [(size_t)TOK * DM];
__device__ __half g_ffh [(size_t)TOK * DFF];
__device__ float  g_x2  [(size_t)TOK * DM];
__device__ __half g_wqkvt[(size_t)3 * DM * DM];   // [3072][1024] K-major
__device__ __half g_w0t [(size_t)DM * DM];
__device__ __half g_w1t [(size_t)DFF * DM];
__device__ __half g_w2t [(size_t)DM * DFF];

// ---------------------------------------------------------------------------
// Helpers
// ---------------------------------------------------------------------------
__device__ __forceinline__ void mma_f16(float* c, const uint32_t* a,
                                        uint32_t b0, uint32_t b1) {
    asm volatile(
        "mma.sync.aligned.m16n8k16.row.col.f32.f16.f16.f32 "
        "{%0,%1,%2,%3}, {%4,%5,%6,%7}, {%8,%9}, {%0,%1,%2,%3};"
        : "+f"(c[0]), "+f"(c[1]), "+f"(c[2]), "+f"(c[3])
        : "r"(a[0]), "r"(a[1]), "r"(a[2]), "r"(a[3]), "r"(b0), "r"(b1));
}
__device__ __forceinline__ uint32_t packh2(float x, float y) {
    __half2 h = __floats2half2_rn(x, y);
    return *(uint32_t*)&h;
}
__device__ __forceinline__ void cpa16(uint32_t dst, const void* src) {
    asm volatile("cp.async.cg.shared.global [%0], [%1], 16;" :: "r"(dst), "l"(src));
}
__device__ __forceinline__ void cpa_commit() {
    asm volatile("cp.async.commit_group;" ::: "memory");
}
__device__ __forceinline__ void cpa_wait1() {
    asm volatile("cp.async.wait_group 1;" ::: "memory");
}
__device__ __forceinline__ void ldm4(uint32_t& r0, uint32_t& r1, uint32_t& r2,
                                     uint32_t& r3, uint32_t addr) {
    asm volatile("ldmatrix.sync.aligned.m8n8.x4.shared.b16 {%0,%1,%2,%3}, [%4];"
                 : "=r"(r0), "=r"(r1), "=r"(r2), "=r"(r3) : "r"(addr));
}

// ---------------------------------------------------------------------------
// fp16 mma GEMM with cp.async 3-stage pipeline + ldmatrix fragments.
// C[M,N] = A[M,K] @ B^T;  A fp16 [M][K] (ld=lda), B fp16 [N][K] (ld=ldb).
// 128x128 tile, BK=32, 256 threads = 8 warps (4M x 2N), warp tile 32x64.
// smem rows padded to 40 halves (ldmatrix conflict-free).
// ---------------------------------------------------------------------------
template<bool BIAS, bool RELU, bool RES, bool OUTH>
__global__ __launch_bounds__(256, 2) void hgemm(
    const __half* __restrict__ A, int lda,
    const __half* __restrict__ B, int ldb,
    void* __restrict__ Cv, int ldc,
    const float* __restrict__ bias, const float* __restrict__ res, int K)
{
    constexpr int BM = 128, BN = 128, BK = 32, SK = 40, STG = 3;
    constexpr int TILE_H = BM * SK;               // halves per stage per operand
    extern __shared__ char smem_raw[];
    __half* As = (__half*)smem_raw;                      // [STG][BM][SK]
    __half* Bs = (__half*)(smem_raw + STG * TILE_H * 2); // [STG][BN][SK]

    const int tid = threadIdx.x;
    const int wid = tid >> 5, lane = tid & 31;
    const int warpM = wid & 3, warpN = wid >> 2;
    const int g = lane >> 2, q4 = lane & 3;

    const __half* Ab = A + (size_t)blockIdx.y * BM * lda;
    const __half* Bb = B + (size_t)blockIdx.x * BN * ldb;

    // cp.async staging map: 512 16B-chunks per operand tile; thread covers
    // chunks tid and tid+256 -> rows r0, r0+64, same 8-half column group.
    const int r0c = tid >> 2, c0 = (tid & 3) * 8;
    const uint32_t as_u32 = (uint32_t)__cvta_generic_to_shared(As);
    const uint32_t bs_u32 = (uint32_t)__cvta_generic_to_shared(Bs);
    const uint32_t dstA = as_u32 + (uint32_t)(r0c * SK + c0) * 2;
    const uint32_t dstB = bs_u32 + (uint32_t)(r0c * SK + c0) * 2;

    // ldmatrix per-lane addresses (byte offsets within a stage)
    const int gsel = lane >> 3, rin = lane & 7;
    // A: matrices {m0..7,k0..7},{m8..15,k0..7},{m0..7,k8..15},{m8..15,k8..15}
    const uint32_t offA = (uint32_t)(((warpM * 32 + (gsel & 1) * 8 + rin) * SK
                                      + (gsel >> 1) * 8) * 2);
    // B: matrices {n0..7,k0..7},{n0..7,k8..15},{n8..15,k0..7},{n8..15,k8..15}
    const uint32_t offB = (uint32_t)(((warpN * 64 + (gsel >> 1) * 8 + rin) * SK
                                      + (gsel & 1) * 8) * 2);

    float acc[2][8][4];
    #pragma unroll
    for (int mt = 0; mt < 2; mt++)
        #pragma unroll
        for (int nt = 0; nt < 8; nt++)
            #pragma unroll
            for (int j = 0; j < 4; j++) acc[mt][nt][j] = 0.0f;

    const int nit = K / BK;

    // prologue: stages 0,1
    #pragma unroll
    for (int ps = 0; ps < 2; ps++) {
        const uint32_t sb = (uint32_t)(ps * TILE_H * 2);
        cpa16(dstA + sb, Ab + (size_t)r0c * lda + ps * BK + c0);
        cpa16(dstA + sb + (uint32_t)(64 * SK * 2), Ab + (size_t)(r0c + 64) * lda + ps * BK + c0);
        cpa16(dstB + sb, Bb + (size_t)r0c * ldb + ps * BK + c0);
        cpa16(dstB + sb + (uint32_t)(64 * SK * 2), Bb + (size_t)(r0c + 64) * ldb + ps * BK + c0);
        cpa_commit();
    }

    for (int t = 0; t < nit; t++) {
        const int buf = t % 3;
        cpa_wait1();          // stage t resident
        __syncthreads();      // all warps done with stage t-1's buffer reuse

        if (t + 2 < nit) {    // refill stage t+2 (buffer consumed at t-1)
            const int ps = (t + 2) % 3;
            const int k0 = (t + 2) * BK;
            const uint32_t sb = (uint32_t)(ps * TILE_H * 2);
            cpa16(dstA + sb, Ab + (size_t)r0c * lda + k0 + c0);
            cpa16(dstA + sb + (uint32_t)(64 * SK * 2), Ab + (size_t)(r0c + 64) * lda + k0 + c0);
            cpa16(dstB + sb, Bb + (size_t)r0c * ldb + k0 + c0);
            cpa16(dstB + sb + (uint32_t)(64 * SK * 2), Bb + (size_t)(r0c + 64) * ldb + k0 + c0);
        }
        cpa_commit();         // always commit (keeps group counting uniform)

        const uint32_t stA = as_u32 + (uint32_t)(buf * TILE_H * 2) + offA;
        const uint32_t stB = bs_u32 + (uint32_t)(buf * TILE_H * 2) + offB;
        #pragma unroll
        for (int ks = 0; ks < 2; ks++) {
            const uint32_t ko = (uint32_t)(ks * 16 * 2);
            uint32_t a[2][4], b[8][2];
            ldm4(a[0][0], a[0][1], a[0][2], a[0][3], stA + ko);
            ldm4(a[1][0], a[1][1], a[1][2], a[1][3], stA + (uint32_t)(16 * SK * 2) + ko);
            #pragma unroll
            for (int p = 0; p < 4; p++)
                ldm4(b[2*p][0], b[2*p][1], b[2*p+1][0], b[2*p+1][1],
                     stB + (uint32_t)(p * 16 * SK * 2) + ko);
            #pragma unroll
            for (int mt = 0; mt < 2; mt++)
                #pragma unroll
                for (int nt = 0; nt < 8; nt++)
                    mma_f16(acc[mt][nt], a[mt], b[nt][0], b[nt][1]);
        }
    }

    // Epilogue
    const int growb = blockIdx.y * BM + warpM * 32;
    const int gcolb = blockIdx.x * BN + warpN * 64;
    #pragma unroll
    for (int mt = 0; mt < 2; mt++) {
        #pragma unroll
        for (int half = 0; half < 2; half++) {
            const int row = growb + mt * 16 + half * 8 + g;
            #pragma unroll
            for (int nt = 0; nt < 8; nt++) {
                const int col = gcolb + nt * 8 + 2 * q4;
                float vx = acc[mt][nt][half * 2 + 0];
                float vy = acc[mt][nt][half * 2 + 1];
                if (BIAS) { vx += bias[col]; vy += bias[col + 1]; }
                if (RES) {
                    const float* rr = res + (size_t)row * ldc + col;
                    vx += rr[0]; vy += rr[1];
                }
                if (RELU) { vx = fmaxf(vx, 0.f); vy = fmaxf(vy, 0.f); }
                if (OUTH) {
                    *(uint32_t*)((__half*)Cv + (size_t)row * ldc + col) = packh2(vx, vy);
                } else {
                    *(float2*)((float*)Cv + (size_t)row * ldc + col) = make_float2(vx, vy);
                }
            }
        }
    }
}

// ---------------------------------------------------------------------------
// Flash attention over packed QKV (ld = 3*DM).  One block = 128 q rows of
// one (n,h).  8 warps x 16 rows; 64-key K/V smem tiles (V transposed at load);
// online softmax; P reused as mma A fragments.
// ---------------------------------------------------------------------------
#define QKVLD (3 * DM)
__global__ __launch_bounds__(256) void flash_attn(
    const __half* __restrict__ QKV, __half* __restrict__ Og)
{
    __shared__ __half Ksm[64][72];
    __shared__ __half Vt [64][72];

    const int tid = threadIdx.x, wid = tid >> 5, lane = tid & 31;
    const int g = lane >> 2, q4 = lane & 3;
    const int h = blockIdx.y, n = blockIdx.z;
    const int q0 = blockIdx.x * 128 + wid * 16;
    const size_t base = (size_t)n * S * QKVLD + h * HD;
    const __half* Qg = QKV + base;
    const __half* Kg = QKV + base + DM;
    const __half* Vg = QKV + base + 2 * DM;

    uint32_t qf[4][4];
    {
        const __half* r0 = Qg + (size_t)(q0 + g) * QKVLD;
        const __half* r1 = Qg + (size_t)(q0 + g + 8) * QKVLD;
        #pragma unroll
        for (int ks = 0; ks < 4; ks++) {
            const int c = ks * 16 + 2 * q4;
            qf[ks][0] = *(const uint32_t*)(r0 + c);
            qf[ks][1] = *(const uint32_t*)(r1 + c);
            qf[ks][2] = *(const uint32_t*)(r0 + c + 8);
            qf[ks][3] = *(const uint32_t*)(r1 + c + 8);
        }
    }

    float o[8][4];
    #pragma unroll
    for (int nd = 0; nd < 8; nd++)
        #pragma unroll
        for (int j = 0; j < 4; j++) o[nd][j] = 0.0f;
    float m0 = -INFINITY, m1 = -INFINITY, l0 = 0.0f, l1 = 0.0f;

    for (int kv = 0; kv < S; kv += 64) {
        #pragma unroll
        for (int i = 0; i < 4; i++) {
            const int idx = tid + i * 256;
            const int r = idx >> 4, cq = idx & 15;
            *(uint2*)&Ksm[r][cq * 4] =
                *(const uint2*)(Kg + (size_t)(kv + r) * QKVLD + cq * 4);
            __half vv[4];
            *(uint2*)vv = *(const uint2*)(Vg + (size_t)(kv + r) * QKVLD + cq * 4);
            Vt[cq * 4 + 0][r] = vv[0];
            Vt[cq * 4 + 1][r] = vv[1];
            Vt[cq * 4 + 2][r] = vv[2];
            Vt[cq * 4 + 3][r] = vv[3];
        }
        __syncthreads();

        float c[8][4];
        #pragma unroll
        for (int nt = 0; nt < 8; nt++)
            #pragma unroll
            for (int j = 0; j < 4; j++) c[nt][j] = 0.0f;
        #pragma unroll
        for (int ks = 0; ks < 4; ks++) {
            const int kk = ks * 16 + 2 * q4;
            #pragma unroll
            for (int nt = 0; nt < 8; nt++) {
                const uint32_t b0 = *(const uint32_t*)&Ksm[nt * 8 + g][kk];
                const uint32_t b1 = *(const uint32_t*)&Ksm[nt * 8 + g][kk + 8];
                mma_f16(c[nt], qf[ks], b0, b1);
            }
        }

        float mx0 = -INFINITY, mx1 = -INFINITY;
        #pragma unroll
        for (int nt = 0; nt < 8; nt++) {
            mx0 = fmaxf(mx0, fmaxf(c[nt][0], c[nt][1]));
            mx1 = fmaxf(mx1, fmaxf(c[nt][2], c[nt][3]));
        }
        mx0 = fmaxf(mx0, __shfl_xor_sync(0xffffffffu, mx0, 1));
        mx0 = fmaxf(mx0, __shfl_xor_sync(0xffffffffu, mx0, 2));
        mx1 = fmaxf(mx1, __shfl_xor_sync(0xffffffffu, mx1, 1));
        mx1 = fmaxf(mx1, __shfl_xor_sync(0xffffffffu, mx1, 2));
        const float nm0 = fmaxf(m0, mx0), nm1 = fmaxf(m1, mx1);
        const float r0 = __expf((m0 - nm0) * 0.125f);
        const float r1 = __expf((m1 - nm1) * 0.125f);
        m0 = nm0; m1 = nm1;

        float s0 = 0.0f, s1 = 0.0f;
        #pragma unroll
        for (int nt = 0; nt < 8; nt++) {
            c[nt][0] = __expf((c[nt][0] - m0) * 0.125f);
            c[nt][1] = __expf((c[nt][1] - m0) * 0.125f);
            c[nt][2] = __expf((c[nt][2] - m1) * 0.125f);
            c[nt][3] = __expf((c[nt][3] - m1) * 0.125f);
            s0 += c[nt][0] + c[nt][1];
            s1 += c[nt][2] + c[nt][3];
        }
        s0 += __shfl_xor_sync(0xffffffffu, s0, 1);
        s0 += __shfl_xor_sync(0xffffffffu, s0, 2);
        s1 += __shfl_xor_sync(0xffffffffu, s1, 1);
        s1 += __shfl_xor_sync(0xffffffffu, s1, 2);
        l0 = l0 * r0 + s0;
        l1 = l1 * r1 + s1;

        #pragma unroll
        for (int nd = 0; nd < 8; nd++) {
            o[nd][0] *= r0; o[nd][1] *= r0;
            o[nd][2] *= r1; o[nd][3] *= r1;
        }

        #pragma unroll
        for (int ks2 = 0; ks2 < 4; ks2++) {
            uint32_t pa[4];
            pa[0] = packh2(c[2 * ks2][0],     c[2 * ks2][1]);
            pa[1] = packh2(c[2 * ks2][2],     c[2 * ks2][3]);
            pa[2] = packh2(c[2 * ks2 + 1][0], c[2 * ks2 + 1][1]);
            pa[3] = packh2(c[2 * ks2 + 1][2], c[2 * ks2 + 1][3]);
            const int kk = ks2 * 16 + 2 * q4;
            #pragma unroll
            for (int nd = 0; nd < 8; nd++) {
                const uint32_t b0 = *(const uint32_t*)&Vt[nd * 8 + g][kk];
                const uint32_t b1 = *(const uint32_t*)&Vt[nd * 8 + g][kk + 8];
                mma_f16(o[nd], pa, b0, b1);
            }
        }
        __syncthreads();
    }

    const float i0 = 1.0f / l0, i1 = 1.0f / l1;
    __half* o0 = Og + (size_t)n * S * DM + h * HD + (size_t)(q0 + g) * DM;
    __half* o1 = o0 + (size_t)8 * DM;
    #pragma unroll
    for (int nd = 0; nd < 8; nd++) {
        const int col = nd * 8 + 2 * q4;
        *(uint32_t*)(o0 + col) = packh2(o[nd][0] * i0, o[nd][1] * i0);
        *(uint32_t*)(o1 + col) = packh2(o[nd][2] * i1, o[nd][3] * i1);
    }
}

// ---------------------------------------------------------------------------
// Transpose fp32 [rows][cols] -> fp16 [cols][rows]
// ---------------------------------------------------------------------------
__global__ __launch_bounds__(256) void transpose_h(
    const float* __restrict__ in, int rows, int cols, __half* __restrict__ out)
{
    __shared__ float t[32][33];
    const int c0 = blockIdx.x * 32, r0 = blockIdx.y * 32;
    const int tx = threadIdx.x & 31, ty = threadIdx.x >> 5;
    #pragma unroll
    for (int i = 0; i < 32; i += 8)
        t[ty + i][tx] = in[(size_t)(r0 + ty + i) * cols + c0 + tx];
    __syncthreads();
    #pragma unroll
    for (int i = 0; i < 32; i += 8)
        out[(size_t)(c0 + ty + i) * rows + r0 + tx] = __float2half(t[tx][ty + i]);
}

// ---------------------------------------------------------------------------
// LayerNorm fp32 in -> fp16 out.  One block per row, 256 threads, float4.
// ---------------------------------------------------------------------------
__global__ __launch_bounds__(256) void ln_h(
    const float* __restrict__ x, const float* __restrict__ g,
    const float* __restrict__ b, __half* __restrict__ y)
{
    const int row = blockIdx.x, t = threadIdx.x;
    float4 v = ((const float4*)(x + (size_t)row * DM))[t];
    float sum = v.x + v.y + v.z + v.w;
    float sq  = v.x*v.x + v.y*v.y + v.z*v.z + v.w*v.w;
    __shared__ float s1[256], s2[256];
    s1[t] = sum; s2[t] = sq;
    __syncthreads();
    #pragma unroll
    for (int st = 128; st > 0; st >>= 1) {
        if (t < st) { s1[t] += s1[t + st]; s2[t] += s2[t + st]; }
        __syncthreads();
    }
    const float mu  = s1[0] * (1.0f / DM);
    const float var = s2[0] * (1.0f / DM) - mu * mu;
    const float inv = rsqrtf(var + LN_EPS);
    const float4 gv = ((const float4*)g)[t];
    const float4 bv = ((const float4*)b)[t];
    uint2 ov;
    ov.x = packh2((v.x - mu) * inv * gv.x + bv.x, (v.y - mu) * inv * gv.y + bv.y);
    ov.y = packh2((v.z - mu) * inv * gv.z + bv.z, (v.w - mu) * inv * gv.w + bv.w);
    ((uint2*)(y + (size_t)row * DM))[t] = ov;
}

// ---------------------------------------------------------------------------
// Launch
// ---------------------------------------------------------------------------
extern "C" void kernel_launch(void* const* d_in, const int* in_sizes, int n_in,
                              void* d_out, int out_size)
{
    const float* x    = (const float*)d_in[0];
    const float* w_q  = (const float*)d_in[2];
    const float* w_k  = (const float*)d_in[3];
    const float* w_v  = (const float*)d_in[4];
    const float* w_0  = (const float*)d_in[5];
    const float* b_0  = (const float*)d_in[6];
    const float* w_1  = (const float*)d_in[7];
    const float* b_1  = (const float*)d_in[8];
    const float* w_2  = (const float*)d_in[9];
    const float* b_2  = (const float*)d_in[10];
    const float* g_1  = (const float*)d_in[11];
    const float* be_1 = (const float*)d_in[12];
    const float* g_2  = (const float*)d_in[13];
    const float* be_2 = (const float*)d_in[14];
    float* out = (float*)d_out;

    __half *xnh, *qkv, *aoh, *ffh, *wqkvt, *w0t, *w1t, *w2t;
    float* x2;
    cudaGetSymbolAddress((void**)&xnh, g_xnh);
    cudaGetSymbolAddress((void**)&qkv, g_qkv);
    cudaGetSymbolAddress((void**)&aoh, g_aoh);
    cudaGetSymbolAddress((void**)&ffh, g_ffh);
    cudaGetSymbolAddress((void**)&x2,  g_x2);
    cudaGetSymbolAddress((void**)&wqkvt, g_wqkvt);
    cudaGetSymbolAddress((void**)&w0t, g_w0t);
    cudaGetSymbolAddress((void**)&w1t, g_w1t);
    cudaGetSymbolAddress((void**)&w2t, g_w2t);

    const int DSMEM = 3 * 128 * 40 * 2 * 2;   // 61440 bytes
    static bool attr_done = false;
    if (!attr_done) {
        cudaFuncSetAttribute(hgemm<false,false,false,true>,
                             cudaFuncAttributeMaxDynamicSharedMemorySize, DSMEM);
        cudaFuncSetAttribute(hgemm<true,false,true,false>,
                             cudaFuncAttributeMaxDynamicSharedMemorySize, DSMEM);
        cudaFuncSetAttribute(hgemm<true,true,false,true>,
                             cudaFuncAttributeMaxDynamicSharedMemorySize, DSMEM);
        attr_done = true;
    }

    // Weight transpose+convert: W[K][N] fp32 -> Wt[N][K] fp16 (QKV packed)
    transpose_h<<<dim3(DM/32,  DM/32),  256>>>(w_q, DM, DM, wqkvt);
    transpose_h<<<dim3(DM/32,  DM/32),  256>>>(w_k, DM, DM, wqkvt + (size_t)DM * DM);
    transpose_h<<<dim3(DM/32,  DM/32),  256>>>(w_v, DM, DM, wqkvt + (size_t)2 * DM * DM);
    transpose_h<<<dim3(DM/32,  DM/32),  256>>>(w_0, DM, DM, w0t);
    transpose_h<<<dim3(DFF/32, DM/32),  256>>>(w_1, DM, DFF, w1t);
    transpose_h<<<dim3(DM/32,  DFF/32), 256>>>(w_2, DFF, DM, w2t);

    // LN1 -> fp16
    ln_h<<<TOK, 256>>>(x, g_1, be_1, xnh);

    // Fused QKV projection: [4096, 3072] = xnh @ Wqkv^T
    hgemm<false,false,false,true><<<dim3(24, 32), 256, DSMEM>>>(
        xnh, DM, wqkvt, DM, qkv, 3 * DM, nullptr, nullptr, DM);

    // Fused attention
    flash_attn<<<dim3(S/128, NH, NB), 256>>>(qkv, aoh);

    // x2 = x + ao @ W0 + b0   (fp32 out)
    hgemm<true,false,true,false><<<dim3(8, 32), 256, DSMEM>>>(
        aoh, DM, w0t, DM, x2, DM, b_0, x, DM);

    // LN2 -> fp16
    ln_h<<<TOK, 256>>>(x2, g_2, be_2, xnh);

    // ff = relu(xn @ W1 + b1)  (fp16 out)
    hgemm<true,true,false,true><<<dim3(32, 32), 256, DSMEM>>>(
        xnh, DM, w1t, DM, ffh, DFF, b_1, nullptr, DM);

    // out = x2 + ff @ W2 + b2  (fp32 out)
    hgemm<true,false,true,false><<<dim3(8, 32), 256, DSMEM>>>(
        ffh, DFF, w2t, DFF, out, DM, b_2, x2, DFF);
}